// round 3
// baseline (speedup 1.0000x reference)
#include <cuda_runtime.h>
#include <cuda_bf16.h>
#include <math.h>

#define EMB   128
#define NUv   100000
#define NVv   50000
#define NEv   500000

// ---------------- scratch (device globals: allocation-guard-safe) ----------
__device__ float g_vt[(size_t)NUv * EMB];   // LN(var) @ W_left + b_left
__device__ float g_et[(size_t)NEv * EMB];   // LN(edge) @ W_edge
__device__ float g_ct[(size_t)NVv * EMB];   // LN(con)  @ W_right (reused pass2)
__device__ float g_agg[(size_t)NUv * EMB];  // segment-sum target (max(NU,NV))

// =====================================================================
// Kernel 1: Y[row] = LN(X[row]; g,b) @ W (+bias)     [N x 128] x [128 x 128]
// block = 256 threads, tile = 64 rows x 128 cols, W in smem.
// warp w owns rows w*8..w*8+7 ; lane owns cols lane*4..lane*4+3
// =====================================================================
__global__ __launch_bounds__(256, 2)
void ln_gemm_kernel(const float* __restrict__ X, const float* __restrict__ W,
                    const float* __restrict__ bias,      // may be null
                    const float* __restrict__ g, const float* __restrict__ b,
                    float* __restrict__ Y, int N)
{
    extern __shared__ float sm[];
    float* Ws = sm;                 // 128*128
    float* Xs = sm + EMB * EMB;     // 64*128

    const int tid  = threadIdx.x;
    const int lane = tid & 31;
    const int warp = tid >> 5;

    // load W (16384 floats) as float4
    {
        const float4* W4  = (const float4*)W;
        float4*       Ws4 = (float4*)Ws;
        #pragma unroll
        for (int i = tid; i < EMB * EMB / 4; i += 256) Ws4[i] = W4[i];
    }

    const int row0 = blockIdx.x * 64;

    // load + LN rows (one warp : 8 rows, lane covers 4 contiguous cols)
    const float4 gv = ((const float4*)g)[lane];
    const float4 bv = ((const float4*)b)[lane];
    #pragma unroll
    for (int r = 0; r < 8; r++) {
        const int row = row0 + warp * 8 + r;
        float4 xv = make_float4(0.f, 0.f, 0.f, 0.f);
        if (row < N) xv = ((const float4*)(X + (size_t)row * EMB))[lane];
        float s  = xv.x + xv.y + xv.z + xv.w;
        float ss = xv.x*xv.x + xv.y*xv.y + xv.z*xv.z + xv.w*xv.w;
        #pragma unroll
        for (int o = 16; o; o >>= 1) {
            s  += __shfl_xor_sync(0xffffffffu, s,  o);
            ss += __shfl_xor_sync(0xffffffffu, ss, o);
        }
        const float mu   = s * (1.f / EMB);
        const float var  = ss * (1.f / EMB) - mu * mu;
        const float rstd = rsqrtf(var + 1e-5f);
        float4 o4;
        o4.x = (xv.x - mu) * rstd * gv.x + bv.x;
        o4.y = (xv.y - mu) * rstd * gv.y + bv.y;
        o4.z = (xv.z - mu) * rstd * gv.z + bv.z;
        o4.w = (xv.w - mu) * rstd * gv.w + bv.w;
        ((float4*)(Xs + (warp * 8 + r) * EMB))[lane] = o4;
    }
    __syncthreads();

    // GEMM: acc[8 rows][4 cols]
    float acc[8][4];
    #pragma unroll
    for (int r = 0; r < 8; r++)
        #pragma unroll
        for (int i = 0; i < 4; i++) acc[r][i] = 0.f;

    for (int k = 0; k < EMB; k += 4) {
        float4 xr[8];
        #pragma unroll
        for (int r = 0; r < 8; r++)
            xr[r] = *(const float4*)(Xs + (warp * 8 + r) * EMB + k);
        #pragma unroll
        for (int kk = 0; kk < 4; kk++) {
            const float4 wv = ((const float4*)(Ws + (k + kk) * EMB))[lane];
            #pragma unroll
            for (int r = 0; r < 8; r++) {
                const float xk = (kk == 0) ? xr[r].x : (kk == 1) ? xr[r].y
                               : (kk == 2) ? xr[r].z : xr[r].w;
                acc[r][0] += xk * wv.x; acc[r][1] += xk * wv.y;
                acc[r][2] += xk * wv.z; acc[r][3] += xk * wv.w;
            }
        }
    }

    float4 bb = make_float4(0.f, 0.f, 0.f, 0.f);
    if (bias) bb = ((const float4*)bias)[lane];
    #pragma unroll
    for (int r = 0; r < 8; r++) {
        const int row = row0 + warp * 8 + r;
        if (row < N) {
            float4 o;
            o.x = acc[r][0] + bb.x; o.y = acc[r][1] + bb.y;
            o.z = acc[r][2] + bb.z; o.w = acc[r][3] + bb.w;
            ((float4*)(Y + (size_t)row * EMB))[lane] = o;
        }
    }
}

// =====================================================================
// Kernel 2: per-edge fused join:
//   x = relu(vt[e_u] + et[e] + ct[e_v]); x = LN(x; g1,b1)
//   y = x @ W_join + b_join;             y = LN(y; g2,b2)
//   atomicAdd(agg[seg[e]], y)   where seg = e_v (pass1) or e_u (pass2)
// =====================================================================
__global__ __launch_bounds__(256, 2)
void edge_join_kernel(const float* __restrict__ vt, const float* __restrict__ et,
                      const float* __restrict__ ct,
                      const int* __restrict__ e_u, const int* __restrict__ e_v,
                      const float* __restrict__ Wj, const float* __restrict__ bj,
                      const float* __restrict__ g1, const float* __restrict__ b1,
                      const float* __restrict__ g2, const float* __restrict__ b2,
                      float* __restrict__ agg, int seg_by_ev, int NE)
{
    extern __shared__ float sm[];
    float* Ws = sm;
    float* Xs = sm + EMB * EMB;
    __shared__ int segs[64];

    const int tid  = threadIdx.x;
    const int lane = tid & 31;
    const int warp = tid >> 5;

    {
        const float4* W4  = (const float4*)Wj;
        float4*       Ws4 = (float4*)Ws;
        #pragma unroll
        for (int i = tid; i < EMB * EMB / 4; i += 256) Ws4[i] = W4[i];
    }

    const int e0 = blockIdx.x * 64;
    const float4 g1v = ((const float4*)g1)[lane];
    const float4 b1v = ((const float4*)b1)[lane];

    #pragma unroll
    for (int r = 0; r < 8; r++) {
        const int e = e0 + warp * 8 + r;
        float4 xv = make_float4(0.f, 0.f, 0.f, 0.f);
        if (e < NE) {
            const int iu = e_u[e];
            const int iv = e_v[e];
            if (lane == 0) segs[warp * 8 + r] = seg_by_ev ? iv : iu;
            const float4 a = ((const float4*)(vt + (size_t)iu * EMB))[lane];
            const float4 m = ((const float4*)(et + (size_t)e  * EMB))[lane];
            const float4 c = ((const float4*)(ct + (size_t)iv * EMB))[lane];
            xv.x = fmaxf(a.x + m.x + c.x, 0.f);
            xv.y = fmaxf(a.y + m.y + c.y, 0.f);
            xv.z = fmaxf(a.z + m.z + c.z, 0.f);
            xv.w = fmaxf(a.w + m.w + c.w, 0.f);
        } else if (lane == 0) {
            segs[warp * 8 + r] = -1;
        }
        float s  = xv.x + xv.y + xv.z + xv.w;
        float ss = xv.x*xv.x + xv.y*xv.y + xv.z*xv.z + xv.w*xv.w;
        #pragma unroll
        for (int o = 16; o; o >>= 1) {
            s  += __shfl_xor_sync(0xffffffffu, s,  o);
            ss += __shfl_xor_sync(0xffffffffu, ss, o);
        }
        const float mu   = s * (1.f / EMB);
        const float rstd = rsqrtf(ss * (1.f / EMB) - mu * mu + 1e-5f);
        float4 o4;
        o4.x = (xv.x - mu) * rstd * g1v.x + b1v.x;
        o4.y = (xv.y - mu) * rstd * g1v.y + b1v.y;
        o4.z = (xv.z - mu) * rstd * g1v.z + b1v.z;
        o4.w = (xv.w - mu) * rstd * g1v.w + b1v.w;
        ((float4*)(Xs + (warp * 8 + r) * EMB))[lane] = o4;
    }
    __syncthreads();

    float acc[8][4];
    #pragma unroll
    for (int r = 0; r < 8; r++)
        #pragma unroll
        for (int i = 0; i < 4; i++) acc[r][i] = 0.f;

    for (int k = 0; k < EMB; k += 4) {
        float4 xr[8];
        #pragma unroll
        for (int r = 0; r < 8; r++)
            xr[r] = *(const float4*)(Xs + (warp * 8 + r) * EMB + k);
        #pragma unroll
        for (int kk = 0; kk < 4; kk++) {
            const float4 wv = ((const float4*)(Ws + (k + kk) * EMB))[lane];
            #pragma unroll
            for (int r = 0; r < 8; r++) {
                const float xk = (kk == 0) ? xr[r].x : (kk == 1) ? xr[r].y
                               : (kk == 2) ? xr[r].z : xr[r].w;
                acc[r][0] += xk * wv.x; acc[r][1] += xk * wv.y;
                acc[r][2] += xk * wv.z; acc[r][3] += xk * wv.w;
            }
        }
    }

    const float4 bjv = ((const float4*)bj)[lane];
    const float4 g2v = ((const float4*)g2)[lane];
    const float4 b2v = ((const float4*)b2)[lane];

    #pragma unroll
    for (int r = 0; r < 8; r++) {
        float y0 = acc[r][0] + bjv.x, y1 = acc[r][1] + bjv.y;
        float y2 = acc[r][2] + bjv.z, y3 = acc[r][3] + bjv.w;
        float s  = y0 + y1 + y2 + y3;
        float ss = y0*y0 + y1*y1 + y2*y2 + y3*y3;
        #pragma unroll
        for (int o = 16; o; o >>= 1) {
            s  += __shfl_xor_sync(0xffffffffu, s,  o);
            ss += __shfl_xor_sync(0xffffffffu, ss, o);
        }
        const float mu   = s * (1.f / EMB);
        const float rstd = rsqrtf(ss * (1.f / EMB) - mu * mu + 1e-5f);
        y0 = (y0 - mu) * rstd * g2v.x + b2v.x;
        y1 = (y1 - mu) * rstd * g2v.y + b2v.y;
        y2 = (y2 - mu) * rstd * g2v.z + b2v.z;
        y3 = (y3 - mu) * rstd * g2v.w + b2v.w;
        const int sg = segs[warp * 8 + r];
        if (sg >= 0) {
            float* p = agg + (size_t)sg * EMB + lane * 4;
            atomicAdd(p + 0, y0);
            atomicAdd(p + 1, y1);
            atomicAdd(p + 2, y2);
            atomicAdd(p + 3, y3);
        }
    }
}

// =====================================================================
// Kernel 3: merge:
//   out = LN(relu(concat([h, agg]) @ W_merge + b_merge); gm, bmln)
//   dst[row] = h[row] + out[row]
// W_merge is [256,128] -> 128KB smem; Xs is [64][256] -> 64KB.
// =====================================================================
__global__ __launch_bounds__(256, 1)
void merge_kernel(const float* __restrict__ h, const float* __restrict__ agg,
                  const float* __restrict__ Wm, const float* __restrict__ bm,
                  const float* __restrict__ gm, const float* __restrict__ bmln,
                  float* __restrict__ dst, int N)
{
    extern __shared__ float sm[];
    float* Ws = sm;                    // 256*128
    float* Xs = sm + 2 * EMB * EMB;    // 64*256

    const int tid  = threadIdx.x;
    const int lane = tid & 31;
    const int warp = tid >> 5;

    {
        const float4* W4  = (const float4*)Wm;
        float4*       Ws4 = (float4*)Ws;
        #pragma unroll
        for (int i = tid; i < 2 * EMB * EMB / 4; i += 256) Ws4[i] = W4[i];
    }

    const int row0 = blockIdx.x * 64;
    #pragma unroll
    for (int r = 0; r < 8; r++) {
        const int row = row0 + warp * 8 + r;
        float4 hv = make_float4(0.f, 0.f, 0.f, 0.f);
        float4 av = make_float4(0.f, 0.f, 0.f, 0.f);
        if (row < N) {
            hv = ((const float4*)(h   + (size_t)row * EMB))[lane];
            av = ((const float4*)(agg + (size_t)row * EMB))[lane];
        }
        ((float4*)(Xs + (warp * 8 + r) * 256))[lane]      = hv;
        ((float4*)(Xs + (warp * 8 + r) * 256 + EMB))[lane] = av;
    }
    __syncthreads();

    float acc[8][4];
    #pragma unroll
    for (int r = 0; r < 8; r++)
        #pragma unroll
        for (int i = 0; i < 4; i++) acc[r][i] = 0.f;

    for (int k = 0; k < 256; k += 4) {
        float4 xr[8];
        #pragma unroll
        for (int r = 0; r < 8; r++)
            xr[r] = *(const float4*)(Xs + (warp * 8 + r) * 256 + k);
        #pragma unroll
        for (int kk = 0; kk < 4; kk++) {
            const float4 wv = ((const float4*)(Ws + (k + kk) * EMB))[lane];
            #pragma unroll
            for (int r = 0; r < 8; r++) {
                const float xk = (kk == 0) ? xr[r].x : (kk == 1) ? xr[r].y
                               : (kk == 2) ? xr[r].z : xr[r].w;
                acc[r][0] += xk * wv.x; acc[r][1] += xk * wv.y;
                acc[r][2] += xk * wv.z; acc[r][3] += xk * wv.w;
            }
        }
    }

    const float4 bmv  = ((const float4*)bm)[lane];
    const float4 gmv  = ((const float4*)gm)[lane];
    const float4 blnv = ((const float4*)bmln)[lane];

    #pragma unroll
    for (int r = 0; r < 8; r++) {
        float y0 = fmaxf(acc[r][0] + bmv.x, 0.f);
        float y1 = fmaxf(acc[r][1] + bmv.y, 0.f);
        float y2 = fmaxf(acc[r][2] + bmv.z, 0.f);
        float y3 = fmaxf(acc[r][3] + bmv.w, 0.f);
        float s  = y0 + y1 + y2 + y3;
        float ss = y0*y0 + y1*y1 + y2*y2 + y3*y3;
        #pragma unroll
        for (int o = 16; o; o >>= 1) {
            s  += __shfl_xor_sync(0xffffffffu, s,  o);
            ss += __shfl_xor_sync(0xffffffffu, ss, o);
        }
        const float mu   = s * (1.f / EMB);
        const float rstd = rsqrtf(ss * (1.f / EMB) - mu * mu + 1e-5f);
        const int row = row0 + warp * 8 + r;
        if (row < N) {
            const float4 hv = ((const float4*)(Xs + (warp * 8 + r) * 256))[lane];
            float4 o;
            o.x = hv.x + ((y0 - mu) * rstd * gmv.x + blnv.x);
            o.y = hv.y + ((y1 - mu) * rstd * gmv.y + blnv.y);
            o.z = hv.z + ((y2 - mu) * rstd * gmv.z + blnv.z);
            o.w = hv.w + ((y3 - mu) * rstd * gmv.w + blnv.w);
            ((float4*)(dst + (size_t)row * EMB))[lane] = o;
        }
    }
}

// =====================================================================
// host
// =====================================================================
extern "C" void kernel_launch(void* const* d_in, const int* in_sizes, int n_in,
                              void* d_out, int out_size)
{
    const float* variable_emb   = (const float*)d_in[0];
    const float* edge_emb       = (const float*)d_in[1];
    const float* constraint_emb = (const float*)d_in[2];
    const int*   e_u            = (const int*)  d_in[3];
    const int*   e_v            = (const int*)  d_in[4];
    const float* W_left   = (const float*)d_in[5];
    const float* b_left   = (const float*)d_in[6];
    const float* W_edge   = (const float*)d_in[7];
    const float* W_right  = (const float*)d_in[8];
    const float* W_join   = (const float*)d_in[9];
    const float* b_join   = (const float*)d_in[10];
    const float* W_merge  = (const float*)d_in[11];
    const float* b_merge  = (const float*)d_in[12];
    const float* g_var    = (const float*)d_in[13];
    const float* b_var    = (const float*)d_in[14];
    const float* g_edge   = (const float*)d_in[15];
    const float* b_edge   = (const float*)d_in[16];
    const float* g_con    = (const float*)d_in[17];
    const float* b_con    = (const float*)d_in[18];
    const float* g_join_ln = (const float*)d_in[19];
    const float* b_join_ln = (const float*)d_in[20];
    const float* g_joint   = (const float*)d_in[21];
    const float* b_joint   = (const float*)d_in[22];
    const float* g_merge   = (const float*)d_in[23];
    const float* b_merge_ln = (const float*)d_in[24];

    float* out_var = (float*)d_out;                         // [NU,128]
    float* out_con = (float*)d_out + (size_t)NUv * EMB;     // [NV,128]

    float *vt, *et, *ct, *agg;
    cudaGetSymbolAddress((void**)&vt,  g_vt);
    cudaGetSymbolAddress((void**)&et,  g_et);
    cudaGetSymbolAddress((void**)&ct,  g_ct);
    cudaGetSymbolAddress((void**)&agg, g_agg);

    const int SM_LN    = (EMB * EMB + 64 * EMB) * sizeof(float);       // 96 KB
    const int SM_MERGE = (2 * EMB * EMB + 64 * 256) * sizeof(float);   // 192 KB

    cudaFuncSetAttribute(ln_gemm_kernel,  cudaFuncAttributeMaxDynamicSharedMemorySize, SM_LN);
    cudaFuncSetAttribute(edge_join_kernel, cudaFuncAttributeMaxDynamicSharedMemorySize, SM_LN);
    cudaFuncSetAttribute(merge_kernel,    cudaFuncAttributeMaxDynamicSharedMemorySize, SM_MERGE);

    const dim3 blk(256);
    const int gb_u = (NUv + 63) / 64;
    const int gb_v = (NVv + 63) / 64;
    const int gb_e = (NEv + 63) / 64;

    // shared pre-transforms (vt and et are identical in both passes)
    ln_gemm_kernel<<<gb_u, blk, SM_LN>>>(variable_emb, W_left, b_left, g_var, b_var, vt, NUv);
    ln_gemm_kernel<<<gb_e, blk, SM_LN>>>(edge_emb, W_edge, nullptr, g_edge, b_edge, et, NEv);
    ln_gemm_kernel<<<gb_v, blk, SM_LN>>>(constraint_emb, W_right, nullptr, g_con, b_con, ct, NVv);

    // ---------------- pass 1: var -> con ----------------
    cudaMemsetAsync(agg, 0, (size_t)NVv * EMB * sizeof(float), 0);
    edge_join_kernel<<<gb_e, blk, SM_LN>>>(vt, et, ct, e_u, e_v, W_join, b_join,
                                           g_join_ln, b_join_ln, g_joint, b_joint,
                                           agg, /*seg_by_ev=*/1, NEv);
    merge_kernel<<<gb_v, blk, SM_MERGE>>>(ct, agg, W_merge, b_merge, g_merge, b_merge_ln,
                                          out_con, NVv);

    // ---------------- pass 2: con -> var ----------------
    ln_gemm_kernel<<<gb_v, blk, SM_LN>>>(out_con, W_right, nullptr, g_con, b_con, ct, NVv);
    cudaMemsetAsync(agg, 0, (size_t)NUv * EMB * sizeof(float), 0);
    edge_join_kernel<<<gb_e, blk, SM_LN>>>(vt, et, ct, e_u, e_v, W_join, b_join,
                                           g_join_ln, b_join_ln, g_joint, b_joint,
                                           agg, /*seg_by_ev=*/0, NEv);
    merge_kernel<<<gb_u, blk, SM_MERGE>>>(vt, agg, W_merge, b_merge, g_merge, b_merge_ln,
                                          out_var, NUv);
}